// round 5
// baseline (speedup 1.0000x reference)
#include <cuda_runtime.h>
#include <cuda_fp16.h>
#include <math.h>

#define BB 8
#define CC 3
#define NF 2
#define H0 512
#define W0 1024

#define L0 (512*1024)
#define L1 (256*512)
#define L2 (128*256)
#define L3 (64*128)

#define PI_F 3.14159265358979323846f

struct __align__(8) H4 { __half2 rg, bp; };

// ---- static device scratch ----
__device__ float g_rr1[BB*CC*L1];
__device__ float g_rr2[BB*CC*L2];
__device__ float g_rr3[BB*CC*L3];
__device__ H4 g_t0_0[BB*L0];
__device__ H4 g_t0_1[BB*L1];
__device__ H4 g_t0_2[BB*L2];
__device__ H4 g_t0_3[BB*L3];
__device__ H4 g_t1_0[BB*L0];
__device__ H4 g_t1_1[BB*L1];
__device__ H4 g_t1_2[BB*L2];
__device__ H4 g_t1_3[BB*L3];
__device__ float g_Rt[BB*NF*12];
__device__ float2 g_lon[1920];
__device__ float2 g_lat[960];

__device__ __forceinline__ H4 pack_h4(float r, float g, float b) {
    H4 o; o.rg = __floats2half2_rn(r, g); o.bp = __floats2half2_rn(b, 0.0f); return o;
}

// ---------------- setup: pose matrices + trig tables + out init ----------------
__global__ void setup_kernel(const float* __restrict__ pose, float* __restrict__ out) {
    int idx = blockIdx.x * blockDim.x + threadIdx.x;
    if (idx == 0) out[0] = 0.0f;
    if (idx < BB*NF) {
        const float* p = pose + idx*6;
        float tx = p[0], ty = p[1], tz = p[2];
        float rx = p[3], ry = p[4], rz = p[5];
        float th = sqrtf(rx*rx + ry*ry + rz*rz);
        float inv = 1.0f / fmaxf(th, 1e-8f);
        float kx = rx*inv, ky = ry*inv, kz = rz*inv;
        float s = sinf(th), c = cosf(th), mc = 1.0f - c;
        float* R = g_Rt + idx*12;
        R[0] = 1.0f + mc*(-(ky*ky + kz*kz));
        R[1] = -s*kz + mc*(kx*ky);
        R[2] =  s*ky + mc*(kx*kz);
        R[3] =  s*kz + mc*(kx*ky);
        R[4] = 1.0f + mc*(-(kx*kx + kz*kz));
        R[5] = -s*kx + mc*(ky*kz);
        R[6] = -s*ky + mc*(kx*kz);
        R[7] =  s*kx + mc*(ky*kz);
        R[8] = 1.0f + mc*(-(kx*kx + ky*ky));
        R[9] = tx; R[10] = ty; R[11] = tz;
    }
    if (idx < 1920) {
        int off, w;
        if (idx < 1024)      { off = 0;    w = 1024; }
        else if (idx < 1536) { off = 1024; w = 512;  }
        else if (idx < 1792) { off = 1536; w = 256;  }
        else                 { off = 1792; w = 128;  }
        int x = idx - off;
        float lon = (((float)x + 0.5f) / (float)w * 2.0f - 1.0f) * PI_F;
        g_lon[idx] = make_float2(sinf(lon), cosf(lon));
    } else if (idx < 1920 + 960) {
        int i2 = idx - 1920;
        int off, h;
        if (i2 < 512)      { off = 0;   h = 512; }
        else if (i2 < 768) { off = 512; h = 256; }
        else if (i2 < 896) { off = 768; h = 128; }
        else               { off = 896; h = 64;  }
        int y = i2 - off;
        float lat = -((((float)y + 0.5f) / (float)h) * 2.0f - 1.0f) * (0.5f * PI_F);
        g_lat[i2] = make_float2(sinf(lat), cosf(lat));
    }
}

// ---------------- fused: planar fp32 targets -> H4 level0 + level1 ----------------
// each thread: 4x2 pixel tile of level0. gridDim.z = 16 (b*2+f)
__global__ void tgt_lvl01(const float* __restrict__ t0src, const float* __restrict__ t1src,
                          H4* __restrict__ d00, H4* __restrict__ d10,
                          H4* __restrict__ d01, H4* __restrict__ d11) {
    int z = blockIdx.z;
    int b = z >> 1, f = z & 1;
    const float* src = (f ? t1src : t0src) + (size_t)b*CC*L0;
    H4* dst0 = (f ? d10 : d00) + (size_t)b*L0;
    H4* dst1 = (f ? d11 : d01) + (size_t)b*L1;
    int tid = blockIdx.x * blockDim.x + threadIdx.x;   // < 65536
    int tx = tid & 255;        // W0/4 = 256
    int ty = tid >> 8;         // < H0/2 = 256
    int x0 = tx * 4, y0 = ty * 2;

    float4 a0 = *(const float4*)(src + (size_t)0*L0 + (size_t)y0*W0 + x0);
    float4 b0 = *(const float4*)(src + (size_t)1*L0 + (size_t)y0*W0 + x0);
    float4 c0 = *(const float4*)(src + (size_t)2*L0 + (size_t)y0*W0 + x0);
    float4 a1 = *(const float4*)(src + (size_t)0*L0 + (size_t)(y0+1)*W0 + x0);
    float4 b1 = *(const float4*)(src + (size_t)1*L0 + (size_t)(y0+1)*W0 + x0);
    float4 c1 = *(const float4*)(src + (size_t)2*L0 + (size_t)(y0+1)*W0 + x0);

    H4* o0 = dst0 + (size_t)y0*W0 + x0;
    H4* o1 = dst0 + (size_t)(y0+1)*W0 + x0;
    o0[0] = pack_h4(a0.x, b0.x, c0.x);
    o0[1] = pack_h4(a0.y, b0.y, c0.y);
    o0[2] = pack_h4(a0.z, b0.z, c0.z);
    o0[3] = pack_h4(a0.w, b0.w, c0.w);
    o1[0] = pack_h4(a1.x, b1.x, c1.x);
    o1[1] = pack_h4(a1.y, b1.y, c1.y);
    o1[2] = pack_h4(a1.z, b1.z, c1.z);
    o1[3] = pack_h4(a1.w, b1.w, c1.w);

    H4* p1 = dst1 + (size_t)ty*(W0/2) + tx*2;
    p1[0] = pack_h4(0.25f*(a0.x + a0.y + a1.x + a1.y),
                    0.25f*(b0.x + b0.y + b1.x + b1.y),
                    0.25f*(c0.x + c0.y + c1.x + c1.y));
    p1[1] = pack_h4(0.25f*(a0.z + a0.w + a1.z + a1.w),
                    0.25f*(b0.z + b0.w + b1.z + b1.w),
                    0.25f*(c0.z + c0.w + c1.z + c1.w));
}

__device__ __forceinline__ float3 h4_to_f3(H4 v) {
    float2 rg = __half22float2(v.rg);
    float2 bp = __half22float2(v.bp);
    return make_float3(rg.x, rg.y, bp.x);
}

// ---------------- fused target levels 2+3 from level1 (both frames via z) ----------------
// thread handles a 4x4 region of level1 -> 2x2 of level2 + 1 pixel of level3
__global__ void tgt_lvl23(const H4* __restrict__ s0, const H4* __restrict__ s1,
                          H4* __restrict__ d20, H4* __restrict__ d21,
                          H4* __restrict__ d30, H4* __restrict__ d31) {
    int idx = blockIdx.x * blockDim.x + threadIdx.x;   // BB*L3 = 65536
    if (idx >= BB*L3) return;
    const H4* l1 = (blockIdx.z ? s1 : s0);
    H4* l2 = (blockIdx.z ? d21 : d20);
    H4* l3 = (blockIdx.z ? d31 : d30);
    const int w3 = 128, w2 = 256, w1 = 512;
    int b = idx / L3, p = idx % L3;
    int x3 = p % w3, y3 = p / w3;
    const H4* base1 = l1 + (size_t)b*L1 + (size_t)(y3*4)*w1 + x3*4;
    H4* base2 = l2 + (size_t)b*L2 + (size_t)(y3*2)*w2 + x3*2;

    float3 acc3 = make_float3(0.f, 0.f, 0.f);
    #pragma unroll
    for (int dy = 0; dy < 2; dy++) {
        #pragma unroll
        for (int dx = 0; dx < 2; dx++) {
            float3 s = make_float3(0.f, 0.f, 0.f);
            #pragma unroll
            for (int iy = 0; iy < 2; iy++) {
                #pragma unroll
                for (int ix = 0; ix < 2; ix++) {
                    float3 v = h4_to_f3(base1[(size_t)(dy*2+iy)*w1 + dx*2+ix]);
                    s.x += v.x; s.y += v.y; s.z += v.z;
                }
            }
            s.x *= 0.25f; s.y *= 0.25f; s.z *= 0.25f;
            base2[(size_t)dy*w2 + dx] = pack_h4(s.x, s.y, s.z);
            acc3.x += s.x; acc3.y += s.y; acc3.z += s.z;
        }
    }
    l3[(size_t)b*L3 + p] = pack_h4(0.25f*acc3.x, 0.25f*acc3.y, 0.25f*acc3.z);
}

// ---------------- ref planar: level 1 ----------------
__global__ void ref_lvl1(const float* __restrict__ src, float* __restrict__ dst) {
    int idx = blockIdx.x * blockDim.x + threadIdx.x;
    if (idx >= BB*CC*L1) return;
    const int w2 = 512, w = 1024;
    int img = idx / L1, p = idx % L1;
    int y = p / w2, x = p % w2;
    const float* s = src + ((size_t)img*512 + y*2) * w + x*2;
    dst[idx] = 0.25f*(s[0] + s[1] + s[w] + s[w+1]);
}

// ---------------- ref planar: fused levels 2+3 ----------------
__global__ void ref_lvl23(const float* __restrict__ rr1, float* __restrict__ rr2,
                          float* __restrict__ rr3) {
    int idx = blockIdx.x * blockDim.x + threadIdx.x;   // BB*CC*L3
    if (idx >= BB*CC*L3) return;
    const int w3 = 128, w2 = 256, w1 = 512;
    int img = idx / L3, p = idx % L3;
    int x3 = p % w3, y3 = p / w3;
    const float* base1 = rr1 + (size_t)img*L1 + (size_t)(y3*4)*w1 + x3*4;
    float* base2 = rr2 + (size_t)img*L2 + (size_t)(y3*2)*w2 + x3*2;
    float acc = 0.0f;
    #pragma unroll
    for (int dy = 0; dy < 2; dy++) {
        #pragma unroll
        for (int dx = 0; dx < 2; dx++) {
            const float* s = base1 + (size_t)(dy*2)*w1 + dx*2;
            float v = 0.25f*(s[0] + s[1] + s[w1] + s[w1+1]);
            base2[(size_t)dy*w2 + dx] = v;
            acc += v;
        }
    }
    rr3[(size_t)img*L3 + p] = 0.25f*acc;
}

// ---------------- fast atan2 (Cephes-style, ~1e-7 rad) ----------------
__device__ __forceinline__ float atan_poly(float x) {
    float z = x * x;
    float r = fmaf(8.05374449538e-2f, z, -1.38776856032e-1f);
    r = fmaf(r, z, 1.99777106478e-1f);
    r = fmaf(r, z, -3.33329491539e-1f);
    return fmaf(r * z, x, x);
}
__device__ __forceinline__ float fast_atan2f(float y, float x) {
    float ay = fabsf(y), ax = fabsf(x);
    float mx = fmaxf(ax, ay), mn = fminf(ax, ay);
    float t = __fdividef(mn, mx);
    float u = __fdividef(t - 1.0f, t + 1.0f);
    bool big = t > 0.41421356f;
    float arg = big ? u : t;
    float r = atan_poly(arg) + (big ? 0.78539816339744831f : 0.0f);
    if (ay > ax) r = 1.57079632679489662f - r;
    if (x < 0.0f) r = PI_F - r;
    return copysignf(r, y);
}

__device__ __forceinline__ void tap(const H4* __restrict__ base, int xi, int yi,
                                    int w, int h, float wt,
                                    float& vx, float& vy, float& vz) {
    if (xi >= 0 && xi < w && yi >= 0 && yi < h) {
        H4 t4 = *(base + (size_t)yi*w + xi);
        float2 rg = __half22float2(t4.rg);
        float2 bp = __half22float2(t4.bp);
        vx += wt * rg.x; vy += wt * rg.y; vz += wt * bp.x;
    }
}

// ---------------- fused reprojection + bilinear + masked L1 + reduce ----------------
__global__ void loss_kernel(const float* __restrict__ depth,
                            const float* __restrict__ mask,
                            const float* __restrict__ rr,
                            const H4* __restrict__ tgA,
                            const H4* __restrict__ tgB,
                            const float2* __restrict__ lonT,
                            const float2* __restrict__ latT,
                            int h, int w, float inv_count,
                            float* __restrict__ out) {
    int idx = blockIdx.x * blockDim.x + threadIdx.x;
    int hw = h * w;
    float acc = 0.0f;
    if (idx < BB*hw) {
        int b = idx / hw;
        int p = idx % hw;
        int y = p / w, x = p % w;
        float d = depth[idx];
        float2 lo2 = __ldg(lonT + x);
        float2 la2 = __ldg(latT + y);
        float px0 = d * (la2.y * lo2.x);
        float py0 = d * la2.x;
        float pz0 = d * (la2.y * lo2.y);
        float r0 = rr[((size_t)b*CC + 0)*hw + p];
        float r1 = rr[((size_t)b*CC + 1)*hw + p];
        float r2 = rr[((size_t)b*CC + 2)*hw + p];
        #pragma unroll
        for (int n = 0; n < NF; n++) {
            const float* Rt = g_Rt + (b*NF + n)*12;
            float px = Rt[0]*px0 + Rt[1]*py0 + Rt[2]*pz0 + Rt[9];
            float py = Rt[3]*px0 + Rt[4]*py0 + Rt[5]*pz0 + Rt[10];
            float pz = Rt[6]*px0 + Rt[7]*py0 + Rt[8]*pz0 + Rt[11];
            float lo = fast_atan2f(px, pz);
            float sxz = sqrtf(px*px + pz*pz);
            float la = fast_atan2f(py, sxz);
            float gx = fmaf(lo, (1.0f/PI_F), 1.0f) * (0.5f * (float)(w - 1));
            float gy = fmaf(la, (2.0f/PI_F), 1.0f) * (0.5f * (float)(h - 1));
            const H4* base = ((n == 0) ? tgA : tgB) + (size_t)b*hw;
            float x0f = floorf(gx), y0f = floorf(gy);
            int ix0 = (int)x0f, iy0 = (int)y0f;
            float fx = gx - x0f, fy = gy - y0f;
            float wa = (1.0f - fx) * (1.0f - fy);
            float wb = (1.0f - fx) * fy;
            float wc = fx * (1.0f - fy);
            float wd = fx * fy;
            float vx = 0.0f, vy = 0.0f, vz = 0.0f;
            tap(base, ix0,   iy0,   w, h, wa, vx, vy, vz);
            tap(base, ix0,   iy0+1, w, h, wb, vx, vy, vz);
            tap(base, ix0+1, iy0,   w, h, wc, vx, vy, vz);
            tap(base, ix0+1, iy0+1, w, h, wd, vx, vy, vz);
            float m = mask[((size_t)(b*NF + n))*hw + p];
            acc += m * (fabsf(r0 - vx) + fabsf(r1 - vy) + fabsf(r2 - vz));
        }
    }
    #pragma unroll
    for (int o = 16; o > 0; o >>= 1) acc += __shfl_down_sync(0xffffffffu, acc, o);
    __shared__ float sh[8];
    int lane = threadIdx.x & 31, wid = threadIdx.x >> 5;
    if (lane == 0) sh[wid] = acc;
    __syncthreads();
    if (wid == 0) {
        acc = (lane < (int)(blockDim.x >> 5)) ? sh[lane] : 0.0f;
        #pragma unroll
        for (int o = 4; o > 0; o >>= 1) acc += __shfl_down_sync(0xffffffffu, acc, o);
        if (lane == 0) atomicAdd(out, acc * inv_count);
    }
}

static inline int cdiv(int a, int b) { return (a + b - 1) / b; }

extern "C" void kernel_launch(void* const* d_in, const int* in_sizes, int n_in,
                              void* d_out, int out_size) {
    const float* ref   = (const float*)d_in[0];
    const float* dep[4] = {(const float*)d_in[1], (const float*)d_in[3],
                           (const float*)d_in[5], (const float*)d_in[7]};
    const float* msk[4] = {(const float*)d_in[2], (const float*)d_in[4],
                           (const float*)d_in[6], (const float*)d_in[8]};
    const float* tgt0  = (const float*)d_in[9];
    const float* tgt1  = (const float*)d_in[10];
    const float* pose  = (const float*)d_in[11];
    float* out = (float*)d_out;

    float *rr1, *rr2, *rr3;
    H4 *t00, *t01, *t02, *t03, *t10, *t11, *t12, *t13;
    float2 *lonT, *latT;
    cudaGetSymbolAddress((void**)&rr1, g_rr1);
    cudaGetSymbolAddress((void**)&rr2, g_rr2);
    cudaGetSymbolAddress((void**)&rr3, g_rr3);
    cudaGetSymbolAddress((void**)&t00, g_t0_0);
    cudaGetSymbolAddress((void**)&t01, g_t0_1);
    cudaGetSymbolAddress((void**)&t02, g_t0_2);
    cudaGetSymbolAddress((void**)&t03, g_t0_3);
    cudaGetSymbolAddress((void**)&t10, g_t1_0);
    cudaGetSymbolAddress((void**)&t11, g_t1_1);
    cudaGetSymbolAddress((void**)&t12, g_t1_2);
    cudaGetSymbolAddress((void**)&t13, g_t1_3);
    cudaGetSymbolAddress((void**)&lonT, g_lon);
    cudaGetSymbolAddress((void**)&latT, g_lat);

    const int T = 256;
    const int lonOff[4] = {0, 1024, 1536, 1792};
    const int latOff[4] = {0, 512, 768, 896};

    setup_kernel<<<12, T>>>(pose, out);

    tgt_lvl01<<<dim3(256, 1, 16), T>>>(tgt0, tgt1, t00, t10, t01, t11);
    tgt_lvl23<<<dim3(cdiv(BB*L3, T), 1, 2), T>>>(t01, t11, t02, t12, t03, t13);

    ref_lvl1<<<cdiv(BB*CC*L1, T), T>>>(ref, rr1);
    ref_lvl23<<<cdiv(BB*CC*L3, T), T>>>(rr1, rr2, rr3);

    loss_kernel<<<cdiv(BB*L0, T), T>>>(dep[0], msk[0], ref, t00, t10,
                                       lonT + lonOff[0], latT + latOff[0],
                                       512, 1024, 1.0f/(float)(BB*CC*L0), out);
    loss_kernel<<<cdiv(BB*L1, T), T>>>(dep[1], msk[1], rr1, t01, t11,
                                       lonT + lonOff[1], latT + latOff[1],
                                       256, 512, 1.0f/(float)(BB*CC*L1), out);
    loss_kernel<<<cdiv(BB*L2, T), T>>>(dep[2], msk[2], rr2, t02, t12,
                                       lonT + lonOff[2], latT + latOff[2],
                                       128, 256, 1.0f/(float)(BB*CC*L2), out);
    loss_kernel<<<cdiv(BB*L3, T), T>>>(dep[3], msk[3], rr3, t03, t13,
                                       lonT + lonOff[3], latT + latOff[3],
                                       64, 128, 1.0f/(float)(BB*CC*L3), out);
}

// round 6
// speedup vs baseline: 1.0046x; 1.0046x over previous
#include <cuda_runtime.h>
#include <cuda_fp16.h>
#include <math.h>

#define BB 8
#define CC 3
#define NF 2
#define H0 512
#define W0 1024

#define L0 (512*1024)
#define L1 (256*512)
#define L2 (128*256)
#define L3 (64*128)

#define PI_F 3.14159265358979323846f

struct __align__(8) H4 { __half2 rg, bp; };

// ---- static device scratch ----
__device__ float g_rr1[BB*CC*L1];
__device__ float g_rr2[BB*CC*L2];
__device__ float g_rr3[BB*CC*L3];
__device__ H4 g_t0_0[BB*L0];
__device__ H4 g_t0_1[BB*L1];
__device__ H4 g_t0_2[BB*L2];
__device__ H4 g_t0_3[BB*L3];
__device__ H4 g_t1_0[BB*L0];
__device__ H4 g_t1_1[BB*L1];
__device__ H4 g_t1_2[BB*L2];
__device__ H4 g_t1_3[BB*L3];
__device__ float g_Rt[BB*NF*12];
__device__ float2 g_lon[1920];
__device__ float2 g_lat[960];

__device__ __forceinline__ H4 pack_h4(float r, float g, float b) {
    H4 o; o.rg = __floats2half2_rn(r, g); o.bp = __floats2half2_rn(b, 0.0f); return o;
}

// ---------------- setup ----------------
__global__ void setup_kernel(const float* __restrict__ pose, float* __restrict__ out) {
    int idx = blockIdx.x * blockDim.x + threadIdx.x;
    if (idx == 0) out[0] = 0.0f;
    if (idx < BB*NF) {
        const float* p = pose + idx*6;
        float tx = p[0], ty = p[1], tz = p[2];
        float rx = p[3], ry = p[4], rz = p[5];
        float th = sqrtf(rx*rx + ry*ry + rz*rz);
        float inv = 1.0f / fmaxf(th, 1e-8f);
        float kx = rx*inv, ky = ry*inv, kz = rz*inv;
        float s = sinf(th), c = cosf(th), mc = 1.0f - c;
        float* R = g_Rt + idx*12;
        R[0] = 1.0f + mc*(-(ky*ky + kz*kz));
        R[1] = -s*kz + mc*(kx*ky);
        R[2] =  s*ky + mc*(kx*kz);
        R[3] =  s*kz + mc*(kx*ky);
        R[4] = 1.0f + mc*(-(kx*kx + kz*kz));
        R[5] = -s*kx + mc*(ky*kz);
        R[6] = -s*ky + mc*(kx*kz);
        R[7] =  s*kx + mc*(ky*kz);
        R[8] = 1.0f + mc*(-(kx*kx + ky*ky));
        R[9] = tx; R[10] = ty; R[11] = tz;
    }
    if (idx < 1920) {
        int off, w;
        if (idx < 1024)      { off = 0;    w = 1024; }
        else if (idx < 1536) { off = 1024; w = 512;  }
        else if (idx < 1792) { off = 1536; w = 256;  }
        else                 { off = 1792; w = 128;  }
        int x = idx - off;
        float lon = (((float)x + 0.5f) / (float)w * 2.0f - 1.0f) * PI_F;
        g_lon[idx] = make_float2(sinf(lon), cosf(lon));
    } else if (idx < 1920 + 960) {
        int i2 = idx - 1920;
        int off, h;
        if (i2 < 512)      { off = 0;   h = 512; }
        else if (i2 < 768) { off = 512; h = 256; }
        else if (i2 < 896) { off = 768; h = 128; }
        else               { off = 896; h = 64;  }
        int y = i2 - off;
        float lat = -((((float)y + 0.5f) / (float)h) * 2.0f - 1.0f) * (0.5f * PI_F);
        g_lat[i2] = make_float2(sinf(lat), cosf(lat));
    }
}

// ---------------- fused: planar fp32 targets -> H4 level0 + level1 ----------------
__global__ void tgt_lvl01(const float* __restrict__ t0src, const float* __restrict__ t1src,
                          H4* __restrict__ d00, H4* __restrict__ d10,
                          H4* __restrict__ d01, H4* __restrict__ d11) {
    int z = blockIdx.z;
    int b = z >> 1, f = z & 1;
    const float* src = (f ? t1src : t0src) + (size_t)b*CC*L0;
    H4* dst0 = (f ? d10 : d00) + (size_t)b*L0;
    H4* dst1 = (f ? d11 : d01) + (size_t)b*L1;
    int tid = blockIdx.x * blockDim.x + threadIdx.x;
    int tx = tid & 255;
    int ty = tid >> 8;
    int x0 = tx * 4, y0 = ty * 2;

    float4 a0 = *(const float4*)(src + (size_t)0*L0 + (size_t)y0*W0 + x0);
    float4 b0 = *(const float4*)(src + (size_t)1*L0 + (size_t)y0*W0 + x0);
    float4 c0 = *(const float4*)(src + (size_t)2*L0 + (size_t)y0*W0 + x0);
    float4 a1 = *(const float4*)(src + (size_t)0*L0 + (size_t)(y0+1)*W0 + x0);
    float4 b1 = *(const float4*)(src + (size_t)1*L0 + (size_t)(y0+1)*W0 + x0);
    float4 c1 = *(const float4*)(src + (size_t)2*L0 + (size_t)(y0+1)*W0 + x0);

    H4* o0 = dst0 + (size_t)y0*W0 + x0;
    H4* o1 = dst0 + (size_t)(y0+1)*W0 + x0;
    o0[0] = pack_h4(a0.x, b0.x, c0.x);
    o0[1] = pack_h4(a0.y, b0.y, c0.y);
    o0[2] = pack_h4(a0.z, b0.z, c0.z);
    o0[3] = pack_h4(a0.w, b0.w, c0.w);
    o1[0] = pack_h4(a1.x, b1.x, c1.x);
    o1[1] = pack_h4(a1.y, b1.y, c1.y);
    o1[2] = pack_h4(a1.z, b1.z, c1.z);
    o1[3] = pack_h4(a1.w, b1.w, c1.w);

    H4* p1 = dst1 + (size_t)ty*(W0/2) + tx*2;
    p1[0] = pack_h4(0.25f*(a0.x + a0.y + a1.x + a1.y),
                    0.25f*(b0.x + b0.y + b1.x + b1.y),
                    0.25f*(c0.x + c0.y + c1.x + c1.y));
    p1[1] = pack_h4(0.25f*(a0.z + a0.w + a1.z + a1.w),
                    0.25f*(b0.z + b0.w + b1.z + b1.w),
                    0.25f*(c0.z + c0.w + c1.z + c1.w));
}

__device__ __forceinline__ float3 h4_to_f3(H4 v) {
    float2 rg = __half22float2(v.rg);
    float2 bp = __half22float2(v.bp);
    return make_float3(rg.x, rg.y, bp.x);
}

// ---------------- fused target levels 2+3 ----------------
__global__ void tgt_lvl23(const H4* __restrict__ s0, const H4* __restrict__ s1,
                          H4* __restrict__ d20, H4* __restrict__ d21,
                          H4* __restrict__ d30, H4* __restrict__ d31) {
    int idx = blockIdx.x * blockDim.x + threadIdx.x;
    if (idx >= BB*L3) return;
    const H4* l1 = (blockIdx.z ? s1 : s0);
    H4* l2 = (blockIdx.z ? d21 : d20);
    H4* l3 = (blockIdx.z ? d31 : d30);
    const int w3 = 128, w2 = 256, w1 = 512;
    int b = idx / L3, p = idx % L3;
    int x3 = p % w3, y3 = p / w3;
    const H4* base1 = l1 + (size_t)b*L1 + (size_t)(y3*4)*w1 + x3*4;
    H4* base2 = l2 + (size_t)b*L2 + (size_t)(y3*2)*w2 + x3*2;

    float3 acc3 = make_float3(0.f, 0.f, 0.f);
    #pragma unroll
    for (int dy = 0; dy < 2; dy++) {
        #pragma unroll
        for (int dx = 0; dx < 2; dx++) {
            float3 s = make_float3(0.f, 0.f, 0.f);
            #pragma unroll
            for (int iy = 0; iy < 2; iy++) {
                #pragma unroll
                for (int ix = 0; ix < 2; ix++) {
                    float3 v = h4_to_f3(base1[(size_t)(dy*2+iy)*w1 + dx*2+ix]);
                    s.x += v.x; s.y += v.y; s.z += v.z;
                }
            }
            s.x *= 0.25f; s.y *= 0.25f; s.z *= 0.25f;
            base2[(size_t)dy*w2 + dx] = pack_h4(s.x, s.y, s.z);
            acc3.x += s.x; acc3.y += s.y; acc3.z += s.z;
        }
    }
    l3[(size_t)b*L3 + p] = pack_h4(0.25f*acc3.x, 0.25f*acc3.y, 0.25f*acc3.z);
}

// ---------------- ref planar: level 1 ----------------
__global__ void ref_lvl1(const float* __restrict__ src, float* __restrict__ dst) {
    int idx = blockIdx.x * blockDim.x + threadIdx.x;
    if (idx >= BB*CC*L1) return;
    const int w2 = 512, w = 1024;
    int img = idx / L1, p = idx % L1;
    int y = p / w2, x = p % w2;
    const float* s = src + ((size_t)img*512 + y*2) * w + x*2;
    dst[idx] = 0.25f*(s[0] + s[1] + s[w] + s[w+1]);
}

// ---------------- ref planar: fused levels 2+3 ----------------
__global__ void ref_lvl23(const float* __restrict__ rr1, float* __restrict__ rr2,
                          float* __restrict__ rr3) {
    int idx = blockIdx.x * blockDim.x + threadIdx.x;
    if (idx >= BB*CC*L3) return;
    const int w3 = 128, w2 = 256, w1 = 512;
    int img = idx / L3, p = idx % L3;
    int x3 = p % w3, y3 = p / w3;
    const float* base1 = rr1 + (size_t)img*L1 + (size_t)(y3*4)*w1 + x3*4;
    float* base2 = rr2 + (size_t)img*L2 + (size_t)(y3*2)*w2 + x3*2;
    float acc = 0.0f;
    #pragma unroll
    for (int dy = 0; dy < 2; dy++) {
        #pragma unroll
        for (int dx = 0; dx < 2; dx++) {
            const float* s = base1 + (size_t)(dy*2)*w1 + dx*2;
            float v = 0.25f*(s[0] + s[1] + s[w1] + s[w1+1]);
            base2[(size_t)dy*w2 + dx] = v;
            acc += v;
        }
    }
    rr3[(size_t)img*L3 + p] = 0.25f*acc;
}

// ---------------- fast atan2, single MUFU divide ----------------
__device__ __forceinline__ float atan_poly(float x) {
    float z = x * x;
    float r = fmaf(8.05374449538e-2f, z, -1.38776856032e-1f);
    r = fmaf(r, z, 1.99777106478e-1f);
    r = fmaf(r, z, -3.33329491539e-1f);
    return fmaf(r * z, x, x);
}
__device__ __forceinline__ float fast_atan2f(float y, float x) {
    float ay = fabsf(y), ax = fabsf(x);
    float mx = fmaxf(ax, ay), mn = fminf(ax, ay);
    bool big = mn > 0.41421356f * mx;
    float num = big ? (mn - mx) : mn;
    float den = big ? (mn + mx) : mx;
    float arg = __fdividef(num, den);
    float r = atan_poly(arg) + (big ? 0.78539816339744831f : 0.0f);
    if (ay > ax) r = 1.57079632679489662f - r;
    if (x < 0.0f) r = PI_F - r;
    return copysignf(r, y);
}
// x >= 0 guaranteed
__device__ __forceinline__ float fast_atan2f_pos(float y, float x) {
    float ay = fabsf(y);
    float mx = fmaxf(x, ay), mn = fminf(x, ay);
    bool big = mn > 0.41421356f * mx;
    float num = big ? (mn - mx) : mn;
    float den = big ? (mn + mx) : mx;
    float arg = __fdividef(num, den);
    float r = atan_poly(arg) + (big ? 0.78539816339744831f : 0.0f);
    if (ay > x) r = 1.57079632679489662f - r;
    return copysignf(r, y);
}

// ---------------- loss kernel, templated on W,H, 2 px/thread ----------------
template <int W, int H>
__global__ void loss_kernel(const float* __restrict__ depth,
                            const float* __restrict__ mask,
                            const float* __restrict__ rr,
                            const H4* __restrict__ tgA,
                            const H4* __restrict__ tgB,
                            const float2* __restrict__ lonT,
                            const float2* __restrict__ latT,
                            float inv_count,
                            float* __restrict__ out) {
    constexpr int HW = W * H;
    int tid = blockIdx.x * blockDim.x + threadIdx.x;
    int pix = tid * 2;
    float acc = 0.0f;
    if (pix < BB*HW) {
        int b = pix / HW;
        int p = pix % HW;          // even
        int y = p / W, x = p % W;
        float2 d2 = *(const float2*)(depth + pix);
        float2 la2 = __ldg(latT + y);
        float2 m0 = *(const float2*)(mask + ((size_t)(b*NF + 0))*HW + p);
        float2 m1 = *(const float2*)(mask + ((size_t)(b*NF + 1))*HW + p);
        float2 r0v = *(const float2*)(rr + ((size_t)b*CC + 0)*HW + p);
        float2 r1v = *(const float2*)(rr + ((size_t)b*CC + 1)*HW + p);
        float2 r2v = *(const float2*)(rr + ((size_t)b*CC + 2)*HW + p);
        float RtL[NF][12];
        #pragma unroll
        for (int n = 0; n < NF; n++)
            #pragma unroll
            for (int q = 0; q < 12; q++) RtL[n][q] = g_Rt[(b*NF + n)*12 + q];
        #pragma unroll
        for (int k = 0; k < 2; k++) {
            float d = k ? d2.y : d2.x;
            float2 lo2 = __ldg(lonT + x + k);
            float px0 = d * (la2.y * lo2.x);
            float py0 = d * la2.x;
            float pz0 = d * (la2.y * lo2.y);
            float r0 = k ? r0v.y : r0v.x;
            float r1 = k ? r1v.y : r1v.x;
            float r2 = k ? r2v.y : r2v.x;
            #pragma unroll
            for (int n = 0; n < NF; n++) {
                const float* Rt = RtL[n];
                float px = Rt[0]*px0 + Rt[1]*py0 + Rt[2]*pz0 + Rt[9];
                float py = Rt[3]*px0 + Rt[4]*py0 + Rt[5]*pz0 + Rt[10];
                float pz = Rt[6]*px0 + Rt[7]*py0 + Rt[8]*pz0 + Rt[11];
                float lo = fast_atan2f(px, pz);
                float sxz = sqrtf(px*px + pz*pz);
                float la = fast_atan2f_pos(py, sxz);
                float gx = fmaf(lo, (1.0f/PI_F), 1.0f) * (0.5f * (float)(W - 1));
                float gy = fmaf(la, (2.0f/PI_F), 1.0f) * (0.5f * (float)(H - 1));
                const H4* base = ((n == 0) ? tgA : tgB) + (size_t)b*HW;
                float x0f = floorf(gx), y0f = floorf(gy);
                int ix0 = (int)x0f, iy0 = (int)y0f;
                float fx = gx - x0f, fy = gy - y0f;
                float wa = (1.0f - fx) * (1.0f - fy);
                float wb = (1.0f - fx) * fy;
                float wc = fx * (1.0f - fy);
                float wd = fx * fy;
                float vx = 0.0f, vy = 0.0f, vz = 0.0f;
                bool xin0 = (unsigned)ix0 < (unsigned)W;
                bool xin1 = (unsigned)(ix0+1) < (unsigned)W;
                bool yin0 = (unsigned)iy0 < (unsigned)H;
                bool yin1 = (unsigned)(iy0+1) < (unsigned)H;
                if (xin0 && yin0) { float3 v = h4_to_f3(base[(size_t)iy0*W + ix0]);
                    vx += wa*v.x; vy += wa*v.y; vz += wa*v.z; }
                if (xin0 && yin1) { float3 v = h4_to_f3(base[(size_t)(iy0+1)*W + ix0]);
                    vx += wb*v.x; vy += wb*v.y; vz += wb*v.z; }
                if (xin1 && yin0) { float3 v = h4_to_f3(base[(size_t)iy0*W + ix0+1]);
                    vx += wc*v.x; vy += wc*v.y; vz += wc*v.z; }
                if (xin1 && yin1) { float3 v = h4_to_f3(base[(size_t)(iy0+1)*W + ix0+1]);
                    vx += wd*v.x; vy += wd*v.y; vz += wd*v.z; }
                float m = n ? (k ? m1.y : m1.x) : (k ? m0.y : m0.x);
                acc += m * (fabsf(r0 - vx) + fabsf(r1 - vy) + fabsf(r2 - vz));
            }
        }
    }
    #pragma unroll
    for (int o = 16; o > 0; o >>= 1) acc += __shfl_down_sync(0xffffffffu, acc, o);
    __shared__ float sh[8];
    int lane = threadIdx.x & 31, wid = threadIdx.x >> 5;
    if (lane == 0) sh[wid] = acc;
    __syncthreads();
    if (wid == 0) {
        acc = (lane < (int)(blockDim.x >> 5)) ? sh[lane] : 0.0f;
        #pragma unroll
        for (int o = 4; o > 0; o >>= 1) acc += __shfl_down_sync(0xffffffffu, acc, o);
        if (lane == 0) atomicAdd(out, acc * inv_count);
    }
}

static inline int cdiv(int a, int b) { return (a + b - 1) / b; }

extern "C" void kernel_launch(void* const* d_in, const int* in_sizes, int n_in,
                              void* d_out, int out_size) {
    const float* ref   = (const float*)d_in[0];
    const float* dep[4] = {(const float*)d_in[1], (const float*)d_in[3],
                           (const float*)d_in[5], (const float*)d_in[7]};
    const float* msk[4] = {(const float*)d_in[2], (const float*)d_in[4],
                           (const float*)d_in[6], (const float*)d_in[8]};
    const float* tgt0  = (const float*)d_in[9];
    const float* tgt1  = (const float*)d_in[10];
    const float* pose  = (const float*)d_in[11];
    float* out = (float*)d_out;

    float *rr1, *rr2, *rr3;
    H4 *t00, *t01, *t02, *t03, *t10, *t11, *t12, *t13;
    float2 *lonT, *latT;
    cudaGetSymbolAddress((void**)&rr1, g_rr1);
    cudaGetSymbolAddress((void**)&rr2, g_rr2);
    cudaGetSymbolAddress((void**)&rr3, g_rr3);
    cudaGetSymbolAddress((void**)&t00, g_t0_0);
    cudaGetSymbolAddress((void**)&t01, g_t0_1);
    cudaGetSymbolAddress((void**)&t02, g_t0_2);
    cudaGetSymbolAddress((void**)&t03, g_t0_3);
    cudaGetSymbolAddress((void**)&t10, g_t1_0);
    cudaGetSymbolAddress((void**)&t11, g_t1_1);
    cudaGetSymbolAddress((void**)&t12, g_t1_2);
    cudaGetSymbolAddress((void**)&t13, g_t1_3);
    cudaGetSymbolAddress((void**)&lonT, g_lon);
    cudaGetSymbolAddress((void**)&latT, g_lat);

    const int T = 256;

    setup_kernel<<<12, T>>>(pose, out);

    tgt_lvl01<<<dim3(256, 1, 16), T>>>(tgt0, tgt1, t00, t10, t01, t11);
    tgt_lvl23<<<dim3(cdiv(BB*L3, T), 1, 2), T>>>(t01, t11, t02, t12, t03, t13);

    ref_lvl1<<<cdiv(BB*CC*L1, T), T>>>(ref, rr1);
    ref_lvl23<<<cdiv(BB*CC*L3, T), T>>>(rr1, rr2, rr3);

    loss_kernel<1024,512><<<cdiv(BB*L0/2, T), T>>>(dep[0], msk[0], ref, t00, t10,
                                       lonT + 0, latT + 0,
                                       1.0f/(float)(BB*CC*L0), out);
    loss_kernel<512,256><<<cdiv(BB*L1/2, T), T>>>(dep[1], msk[1], rr1, t01, t11,
                                       lonT + 1024, latT + 512,
                                       1.0f/(float)(BB*CC*L1), out);
    loss_kernel<256,128><<<cdiv(BB*L2/2, T), T>>>(dep[2], msk[2], rr2, t02, t12,
                                       lonT + 1536, latT + 768,
                                       1.0f/(float)(BB*CC*L2), out);
    loss_kernel<128,64><<<cdiv(BB*L3/2, T), T>>>(dep[3], msk[3], rr3, t03, t13,
                                       lonT + 1792, latT + 896,
                                       1.0f/(float)(BB*CC*L3), out);
}